// round 3
// baseline (speedup 1.0000x reference)
#include <cuda_runtime.h>
#include <math.h>

#define BB   2
#define LL   2048
#define SS   2048
#define DD   768
#define HH   12
#define HDIM 64
#define MTOT (BB*LL)   // 4096

// ---------------- scratch (no allocations allowed) ----------------
__device__ float g_Q [(size_t)BB*HH*LL*HDIM];   // (b,h,l,hd)
__device__ float g_K [(size_t)BB*HH*SS*HDIM];
__device__ float g_V [(size_t)BB*HH*SS*HDIM];
__device__ float g_AO[(size_t)MTOT*DD];         // attention out, (b,l,d)
__device__ float g_X [(size_t)MTOT*DD];         // pre-LN residual

// =================== QKV projection GEMM ===================
// C[m,n] = sum_k A[m,k] * W[n,k]; M=4096, N=768, K=768
// 64x64 tile, BK=16, 256 threads, 4x4 micro-tile
__global__ __launch_bounds__(256) void qkv_kernel(
    const float* __restrict__ qin, const float* __restrict__ kin, const float* __restrict__ vin,
    const float* __restrict__ Wq,  const float* __restrict__ Wk,  const float* __restrict__ Wv)
{
    __shared__ float As[16][68];
    __shared__ float Bs[16][68];
    int which = blockIdx.z;
    const float* A  = (which == 0) ? qin : (which == 1) ? kin : vin;
    const float* Wt = (which == 0) ? Wq  : (which == 1) ? Wk  : Wv;
    float* Out      = (which == 0) ? g_Q : (which == 1) ? g_K : g_V;

    int tid = threadIdx.x;
    int tx = tid & 15, ty = tid >> 4;
    int m0 = blockIdx.x * 64, n0 = blockIdx.y * 64;
    int lr = tid >> 2, lc = (tid & 3) * 4;

    const float* Ap = A  + (size_t)(m0 + lr) * DD + lc;
    const float* Bp = Wt + (size_t)(n0 + lr) * DD + lc;

    float acc[4][4] = {};
    for (int k0 = 0; k0 < DD; k0 += 16) {
        float4 a4 = *(const float4*)(Ap + k0);
        float4 b4 = *(const float4*)(Bp + k0);
        As[lc+0][lr]=a4.x; As[lc+1][lr]=a4.y; As[lc+2][lr]=a4.z; As[lc+3][lr]=a4.w;
        Bs[lc+0][lr]=b4.x; Bs[lc+1][lr]=b4.y; Bs[lc+2][lr]=b4.z; Bs[lc+3][lr]=b4.w;
        __syncthreads();
        #pragma unroll
        for (int kk = 0; kk < 16; kk++) {
            float4 av = *(const float4*)&As[kk][ty*4];
            float4 bv = *(const float4*)&Bs[kk][tx*4];
            float a [4] = {av.x, av.y, av.z, av.w};
            float bb2[4] = {bv.x, bv.y, bv.z, bv.w};
            #pragma unroll
            for (int i = 0; i < 4; i++)
                #pragma unroll
                for (int j = 0; j < 4; j++)
                    acc[i][j] += a[i] * bb2[j];
        }
        __syncthreads();
    }
    #pragma unroll
    for (int i = 0; i < 4; i++) {
        int m  = m0 + ty*4 + i;
        int bb = m >> 11, l = m & (LL - 1);
        #pragma unroll
        for (int j = 0; j < 4; j++) {
            int n  = n0 + tx*4 + j;
            int h  = n >> 6, hd = n & 63;
            Out[(((size_t)bb*HH + h)*LL + l)*HDIM + hd] = acc[i][j];
        }
    }
}

// =================== flash attention (fp32) ===================
// grid: (L/64, B*H), 128 threads; thread grid (ty 0..15 -> 4 rows, tx 0..7 -> 8 cols)
#define ATTN_SMEM ((64*68 + 64*64 + 64*68 + 64*68 + 64) * 4)

__global__ __launch_bounds__(128) void attn_kernel(const int* __restrict__ maskp)
{
    extern __shared__ float sm[];
    float* Qs  = sm;              // [64][68] natural (row, d)
    float* KsT = Qs  + 64*68;     // [64][64] d-major
    float* Vs  = KsT + 64*64;     // [64][68] natural (key, d)
    float* Ps  = Vs  + 64*68;     // [64][68]
    float* mk  = Ps  + 64*68;     // [64]

    int tid = threadIdx.x;
    int tx = tid & 7, ty = tid >> 3;
    int bh = blockIdx.y;
    int b  = bh / HH;
    int q0 = blockIdx.x * 64;

    const float* Qg = g_Q + (size_t)bh * LL * HDIM;
    const float* Kg = g_K + (size_t)bh * SS * HDIM;
    const float* Vg = g_V + (size_t)bh * SS * HDIM;

    int lrow = tid & 63, lhalf = tid >> 6;

    // load Q tile
    {
        const float4* src = (const float4*)(Qg + (size_t)(q0 + lrow) * HDIM);
        #pragma unroll
        for (int i = 0; i < 8; i++) {
            int c4 = lhalf * 8 + i;
            *(float4*)&Qs[lrow*68 + c4*4] = src[c4];
        }
    }

    float mold[4], lsum[4], acc[4][8];
    #pragma unroll
    for (int i = 0; i < 4; i++) {
        mold[i] = -1e30f; lsum[i] = 0.f;
        #pragma unroll
        for (int c = 0; c < 8; c++) acc[i][c] = 0.f;
    }

    for (int s0 = 0; s0 < SS; s0 += 64) {
        // load K (transposed to d-major), V (natural), mask
        {
            const float4* ks = (const float4*)(Kg + (size_t)(s0 + lrow) * HDIM);
            const float4* vs = (const float4*)(Vg + (size_t)(s0 + lrow) * HDIM);
            #pragma unroll
            for (int i = 0; i < 8; i++) {
                int c4 = lhalf * 8 + i;
                float4 kv = ks[c4];
                KsT[(c4*4+0)*64 + lrow] = kv.x;
                KsT[(c4*4+1)*64 + lrow] = kv.y;
                KsT[(c4*4+2)*64 + lrow] = kv.z;
                KsT[(c4*4+3)*64 + lrow] = kv.w;
                *(float4*)&Vs[lrow*68 + c4*4] = vs[c4];
            }
            if (tid < 64)
                mk[tid] = (1.0f - (float)maskp[(size_t)b*SS + s0 + tid]) * (-1000000.0f);
        }
        __syncthreads();

        // scores S = Q K^T  (4x8 per thread)
        float s[4][8];
        #pragma unroll
        for (int i = 0; i < 4; i++)
            #pragma unroll
            for (int j = 0; j < 8; j++) s[i][j] = 0.f;

        for (int d = 0; d < 64; d += 4) {
            float qreg[4][4];
            #pragma unroll
            for (int i = 0; i < 4; i++) {
                float4 t = *(const float4*)&Qs[(4*ty+i)*68 + d];
                qreg[i][0]=t.x; qreg[i][1]=t.y; qreg[i][2]=t.z; qreg[i][3]=t.w;
            }
            #pragma unroll
            for (int dd = 0; dd < 4; dd++) {
                float4 ka = *(const float4*)&KsT[(d+dd)*64 + 8*tx];
                float4 kb = *(const float4*)&KsT[(d+dd)*64 + 8*tx + 4];
                float kr[8] = {ka.x,ka.y,ka.z,ka.w,kb.x,kb.y,kb.z,kb.w};
                #pragma unroll
                for (int i = 0; i < 4; i++) {
                    float qv = qreg[i][dd];
                    #pragma unroll
                    for (int j = 0; j < 8; j++)
                        s[i][j] += qv * kr[j];
                }
            }
        }

        // scale + mask + online softmax (rows shared by 8 lanes -> shfl groups of 8)
        #pragma unroll
        for (int i = 0; i < 4; i++) {
            #pragma unroll
            for (int j = 0; j < 8; j++)
                s[i][j] = s[i][j] * 0.125f + mk[8*tx + j];
            float rmax = s[i][0];
            #pragma unroll
            for (int j = 1; j < 8; j++) rmax = fmaxf(rmax, s[i][j]);
            #pragma unroll
            for (int off = 1; off < 8; off <<= 1)
                rmax = fmaxf(rmax, __shfl_xor_sync(0xffffffffu, rmax, off));
            float mnew = fmaxf(mold[i], rmax);
            float corr = __expf(mold[i] - mnew);
            mold[i] = mnew;
            float rsum = 0.f;
            #pragma unroll
            for (int j = 0; j < 8; j++) {
                float p = __expf(s[i][j] - mnew);
                s[i][j] = p;
                rsum += p;
            }
            #pragma unroll
            for (int off = 1; off < 8; off <<= 1)
                rsum += __shfl_xor_sync(0xffffffffu, rsum, off);
            lsum[i] = lsum[i] * corr + rsum;
            #pragma unroll
            for (int c = 0; c < 8; c++) acc[i][c] *= corr;
            *(float4*)&Ps[(4*ty+i)*68 + 8*tx]     = make_float4(s[i][0],s[i][1],s[i][2],s[i][3]);
            *(float4*)&Ps[(4*ty+i)*68 + 8*tx + 4] = make_float4(s[i][4],s[i][5],s[i][6],s[i][7]);
        }
        __syncthreads();

        // acc += P @ V
        for (int j = 0; j < 64; j += 4) {
            float preg[4][4];
            #pragma unroll
            for (int i = 0; i < 4; i++) {
                float4 t = *(const float4*)&Ps[(4*ty+i)*68 + j];
                preg[i][0]=t.x; preg[i][1]=t.y; preg[i][2]=t.z; preg[i][3]=t.w;
            }
            #pragma unroll
            for (int jj = 0; jj < 4; jj++) {
                float4 va = *(const float4*)&Vs[(j+jj)*68 + 8*tx];
                float4 vb = *(const float4*)&Vs[(j+jj)*68 + 8*tx + 4];
                float vr[8] = {va.x,va.y,va.z,va.w,vb.x,vb.y,vb.z,vb.w};
                #pragma unroll
                for (int i = 0; i < 4; i++) {
                    float pv = preg[i][jj];
                    #pragma unroll
                    for (int c = 0; c < 8; c++)
                        acc[i][c] += pv * vr[c];
                }
            }
        }
        __syncthreads();
    }

    // epilogue: normalize, write merged-head layout (b,l,d)
    int h = bh % HH;
    #pragma unroll
    for (int i = 0; i < 4; i++) {
        float inv = 1.0f / lsum[i];
        int row = q0 + 4*ty + i;
        float* dst = g_AO + ((size_t)b*LL + row)*DD + h*HDIM + 8*tx;
        *(float4*)dst     = make_float4(acc[i][0]*inv, acc[i][1]*inv, acc[i][2]*inv, acc[i][3]*inv);
        *(float4*)(dst+4) = make_float4(acc[i][4]*inv, acc[i][5]*inv, acc[i][6]*inv, acc[i][7]*inv);
    }
}

// =================== output projection + bias + residual ===================
__global__ __launch_bounds__(256) void outproj_kernel(
    const float* __restrict__ qin, const float* __restrict__ W,
    const float* __restrict__ bias)
{
    __shared__ float As[16][68];
    __shared__ float Bs[16][68];
    int tid = threadIdx.x;
    int tx = tid & 15, ty = tid >> 4;
    int m0 = blockIdx.x * 64, n0 = blockIdx.y * 64;
    int lr = tid >> 2, lc = (tid & 3) * 4;

    const float* Ap = g_AO + (size_t)(m0 + lr) * DD + lc;
    const float* Bp = W    + (size_t)(n0 + lr) * DD + lc;

    float acc[4][4] = {};
    for (int k0 = 0; k0 < DD; k0 += 16) {
        float4 a4 = *(const float4*)(Ap + k0);
        float4 b4 = *(const float4*)(Bp + k0);
        As[lc+0][lr]=a4.x; As[lc+1][lr]=a4.y; As[lc+2][lr]=a4.z; As[lc+3][lr]=a4.w;
        Bs[lc+0][lr]=b4.x; Bs[lc+1][lr]=b4.y; Bs[lc+2][lr]=b4.z; Bs[lc+3][lr]=b4.w;
        __syncthreads();
        #pragma unroll
        for (int kk = 0; kk < 16; kk++) {
            float4 av = *(const float4*)&As[kk][ty*4];
            float4 bv = *(const float4*)&Bs[kk][tx*4];
            float a [4] = {av.x, av.y, av.z, av.w};
            float bb2[4] = {bv.x, bv.y, bv.z, bv.w};
            #pragma unroll
            for (int i = 0; i < 4; i++)
                #pragma unroll
                for (int j = 0; j < 4; j++)
                    acc[i][j] += a[i] * bb2[j];
        }
        __syncthreads();
    }
    #pragma unroll
    for (int i = 0; i < 4; i++) {
        int m = m0 + ty*4 + i;
        #pragma unroll
        for (int j = 0; j < 4; j++) {
            int n = n0 + tx*4 + j;
            g_X[(size_t)m*DD + n] = acc[i][j] + bias[n] + qin[(size_t)m*DD + n];
        }
    }
}

// =================== LayerNorm ===================
__global__ __launch_bounds__(256) void ln_kernel(
    const float* __restrict__ gamma, const float* __restrict__ beta,
    float* __restrict__ out)
{
    __shared__ float sh[18];
    int row = blockIdx.x, tid = threadIdx.x;
    const float* x = g_X + (size_t)row * DD;
    float v0 = x[tid], v1 = x[tid+256], v2 = x[tid+512];
    float s  = v0 + v1 + v2;
    float sq = v0*v0 + v1*v1 + v2*v2;
    #pragma unroll
    for (int off = 16; off > 0; off >>= 1) {
        s  += __shfl_xor_sync(0xffffffffu, s,  off);
        sq += __shfl_xor_sync(0xffffffffu, sq, off);
    }
    int wid = tid >> 5;
    if ((tid & 31) == 0) { sh[wid] = s; sh[wid + 8] = sq; }
    __syncthreads();
    if (tid == 0) {
        float S = 0.f, Q2 = 0.f;
        #pragma unroll
        for (int i = 0; i < 8; i++) { S += sh[i]; Q2 += sh[i+8]; }
        float mu  = S  * (1.0f / 768.0f);
        float var = Q2 * (1.0f / 768.0f) - mu * mu;
        sh[16] = mu;
        sh[17] = rsqrtf(var + 1e-5f);
    }
    __syncthreads();
    float mu = sh[16], rstd = sh[17];
    float* o = out + (size_t)row * DD;
    o[tid]     = (v0 - mu) * rstd * gamma[tid]     + beta[tid];
    o[tid+256] = (v1 - mu) * rstd * gamma[tid+256] + beta[tid+256];
    o[tid+512] = (v2 - mu) * rstd * gamma[tid+512] + beta[tid+512];
}

// =================== launch ===================
extern "C" void kernel_launch(void* const* d_in, const int* in_sizes, int n_in,
                              void* d_out, int out_size)
{
    const float* q     = (const float*)d_in[0];
    const float* k     = (const float*)d_in[1];
    const float* v     = (const float*)d_in[2];
    const int*   mask  = (const int*)  d_in[3];
    const float* Wq    = (const float*)d_in[4];
    const float* Wk    = (const float*)d_in[5];
    const float* Wv    = (const float*)d_in[6];
    const float* W     = (const float*)d_in[7];
    const float* bias  = (const float*)d_in[8];
    const float* gamma = (const float*)d_in[9];
    const float* beta  = (const float*)d_in[10];
    float* out = (float*)d_out;

    cudaFuncSetAttribute(attn_kernel, cudaFuncAttributeMaxDynamicSharedMemorySize, ATTN_SMEM);

    qkv_kernel   <<<dim3(MTOT/64, DD/64, 3), 256>>>(q, k, v, Wq, Wk, Wv);
    attn_kernel  <<<dim3(LL/64, BB*HH), 128, ATTN_SMEM>>>(mask);
    outproj_kernel<<<dim3(MTOT/64, DD/64), 256>>>(q, W, bias);
    ln_kernel    <<<MTOT, 256>>>(gamma, beta, out);
}

// round 4
// speedup vs baseline: 2.7143x; 2.7143x over previous
#include <cuda_runtime.h>
#include <math.h>

#define BB   2
#define LL   2048
#define SS   2048
#define DD   768
#define HH   12
#define HDIM 64
#define MTOT (BB*LL)   // 4096

// ---------------- scratch (no allocations allowed) ----------------
__device__ float g_Q [(size_t)BB*HH*LL*HDIM];   // (b,h,l,hd)
__device__ float g_K [(size_t)BB*HH*SS*HDIM];
__device__ float g_V [(size_t)BB*HH*SS*HDIM];
__device__ float g_AO[(size_t)MTOT*DD];         // attention out, (b,l,d)
__device__ float g_X [(size_t)MTOT*DD];         // pre-LN residual

// ---------------- tf32 mma helpers ----------------
__device__ __forceinline__ unsigned tf32cvt(float x) {
    unsigned u; asm("cvt.rna.tf32.f32 %0, %1;" : "=r"(u) : "f"(x)); return u;
}
__device__ __forceinline__ uint4 tf32cvt4(float4 v) {
    return make_uint4(tf32cvt(v.x), tf32cvt(v.y), tf32cvt(v.z), tf32cvt(v.w));
}
// D = A(16x8,row) * B(8x8,col) + D, tf32 in, f32 acc
__device__ __forceinline__ void mma8(float* c, const unsigned* a, const unsigned* b) {
    asm volatile(
        "mma.sync.aligned.m16n8k8.row.col.f32.tf32.tf32.f32 "
        "{%0,%1,%2,%3},{%4,%5,%6,%7},{%8,%9},{%0,%1,%2,%3};"
        : "+f"(c[0]), "+f"(c[1]), "+f"(c[2]), "+f"(c[3])
        : "r"(a[0]), "r"(a[1]), "r"(a[2]), "r"(a[3]), "r"(b[0]), "r"(b[1]));
}

// =================== QKV projection GEMM (tf32 mma) ===================
// C[m,n] = sum_k A[m,k] * W[n,k]; M=4096, N=768, K=768
// block: 256 threads (8 warps, 4x2), BM=128, BN=64, BK=32; warp = 32x32
__global__ __launch_bounds__(256) void qkv_mma_kernel(
    const float* __restrict__ qin, const float* __restrict__ kin, const float* __restrict__ vin,
    const float* __restrict__ Wq,  const float* __restrict__ Wk,  const float* __restrict__ Wv)
{
    __shared__ unsigned As[128][36];
    __shared__ unsigned Bs[64][36];

    int which = blockIdx.z;
    const float* A  = (which == 0) ? qin : (which == 1) ? kin : vin;
    const float* Wt = (which == 0) ? Wq  : (which == 1) ? Wk  : Wv;
    float* Out      = (which == 0) ? g_Q : (which == 1) ? g_K : g_V;

    int tid = threadIdx.x, w = tid >> 5, lane = tid & 31;
    int g = lane >> 2, t = lane & 3;
    int wm = w & 3, wn = w >> 2;
    int m0 = blockIdx.x * 128, n0 = blockIdx.y * 64;

    int lr  = tid >> 3;        // 0..31
    int lc4 = (tid & 7) * 4;   // 0..28
    const float* Ap = A  + (size_t)(m0 + lr) * DD + lc4;
    const float* Bp = Wt + (size_t)(n0 + lr) * DD + lc4;

    float c[2][4][4] = {};

    for (int k0 = 0; k0 < DD; k0 += 32) {
        #pragma unroll
        for (int i = 0; i < 4; i++) {
            float4 v = *(const float4*)(Ap + (size_t)i*32*DD + k0);
            *(uint4*)&As[lr + i*32][lc4] = tf32cvt4(v);
        }
        #pragma unroll
        for (int i = 0; i < 2; i++) {
            float4 v = *(const float4*)(Bp + (size_t)i*32*DD + k0);
            *(uint4*)&Bs[lr + i*32][lc4] = tf32cvt4(v);
        }
        __syncthreads();
        #pragma unroll
        for (int ks = 0; ks < 4; ks++) {
            int kk = ks*8 + t;
            unsigned a[2][4], b[4][2];
            #pragma unroll
            for (int mt = 0; mt < 2; mt++) {
                int r = wm*32 + mt*16 + g;
                a[mt][0] = As[r  ][kk];
                a[mt][1] = As[r+8][kk];
                a[mt][2] = As[r  ][kk+4];
                a[mt][3] = As[r+8][kk+4];
            }
            #pragma unroll
            for (int nt = 0; nt < 4; nt++) {
                int r = wn*32 + nt*8 + g;
                b[nt][0] = Bs[r][kk];
                b[nt][1] = Bs[r][kk+4];
            }
            #pragma unroll
            for (int mt = 0; mt < 2; mt++)
                #pragma unroll
                for (int nt = 0; nt < 4; nt++)
                    mma8(c[mt][nt], a[mt], b[nt]);
        }
        __syncthreads();
    }

    // epilogue: write (b,h,l,hd) layout
    #pragma unroll
    for (int mt = 0; mt < 2; mt++) {
        #pragma unroll
        for (int nt = 0; nt < 4; nt++) {
            int m = m0 + wm*32 + mt*16 + g;
            int n = n0 + wn*32 + nt*8 + 2*t;
            int h = n >> 6, hd = n & 63;
            {
                int bb = m >> 11, l = m & (LL-1);
                float* dst = Out + (((size_t)bb*HH + h)*LL + l)*HDIM + hd;
                *(float2*)dst = make_float2(c[mt][nt][0], c[mt][nt][1]);
            }
            {
                int m2 = m + 8;
                int bb = m2 >> 11, l = m2 & (LL-1);
                float* dst = Out + (((size_t)bb*HH + h)*LL + l)*HDIM + hd;
                *(float2*)dst = make_float2(c[mt][nt][2], c[mt][nt][3]);
            }
        }
    }
}

// =================== flash attention (tf32 mma) ===================
// grid: (L/64, B*H), 128 threads (4 warps; warp w owns q-rows w*16..w*16+15)
#define ASTRIDE 68
#define ATTN_SMEM ((64*ASTRIDE*4 + 64) * 4)

__global__ __launch_bounds__(128) void attn_mma_kernel(const int* __restrict__ maskp)
{
    extern __shared__ unsigned smu[];
    unsigned* Qs = smu;                 // [64][68] (row, d)  tf32
    unsigned* Ks = Qs + 64*ASTRIDE;     // [64][68] (key, d)  tf32
    unsigned* Vt = Ks + 64*ASTRIDE;     // [64][68] (d, key)  tf32 (V transposed)
    unsigned* Ps = Vt + 64*ASTRIDE;     // [64][68] (row, key) tf32
    float*    mk = (float*)(Ps + 64*ASTRIDE);  // [64]

    int tid = threadIdx.x, w = tid >> 5, lane = tid & 31;
    int g = lane >> 2, t = lane & 3;
    int bh = blockIdx.y;
    int b  = bh / HH, h = bh % HH;
    int q0 = blockIdx.x * 64;

    const float* Qg = g_Q + (size_t)bh * LL * HDIM;
    const float* Kg = g_K + (size_t)bh * SS * HDIM;
    const float* Vg = g_V + (size_t)bh * SS * HDIM;

    int lrow = tid & 63, half = tid >> 6;

    // load Q tile (once), convert to tf32
    {
        const float4* src = (const float4*)(Qg + (size_t)(q0 + lrow) * HDIM);
        #pragma unroll
        for (int i = 0; i < 8; i++) {
            int c4 = half*8 + i;
            *(uint4*)&Qs[lrow*ASTRIDE + c4*4] = tf32cvt4(src[c4]);
        }
    }

    float o[8][4] = {};
    float mold0 = -1e30f, mold1 = -1e30f, l0 = 0.f, l1 = 0.f;

    const unsigned* qr0 = &Qs[(w*16 + g)*ASTRIDE];
    const unsigned* qr1 = qr0 + 8*ASTRIDE;
    unsigned* pr0 = &Ps[(w*16 + g)*ASTRIDE];
    unsigned* pr1 = pr0 + 8*ASTRIDE;

    for (int s0 = 0; s0 < SS; s0 += 64) {
        // load K (natural), V (transposed), mask
        {
            const float4* ks = (const float4*)(Kg + (size_t)(s0 + lrow) * HDIM);
            const float4* vs = (const float4*)(Vg + (size_t)(s0 + lrow) * HDIM);
            #pragma unroll
            for (int i = 0; i < 8; i++) {
                int c4 = half*8 + i;
                *(uint4*)&Ks[lrow*ASTRIDE + c4*4] = tf32cvt4(ks[c4]);
                float4 vv = vs[c4];
                Vt[(c4*4+0)*ASTRIDE + lrow] = tf32cvt(vv.x);
                Vt[(c4*4+1)*ASTRIDE + lrow] = tf32cvt(vv.y);
                Vt[(c4*4+2)*ASTRIDE + lrow] = tf32cvt(vv.z);
                Vt[(c4*4+3)*ASTRIDE + lrow] = tf32cvt(vv.w);
            }
            if (tid < 64)
                mk[tid] = (1.0f - (float)maskp[(size_t)b*SS + s0 + tid]) * (-1000000.0f);
        }
        __syncthreads();

        // scores: S(16x64) = Q(16x64) K^T   (warp-level, 8 ksteps x 8 ntiles)
        float sc[8][4] = {};
        #pragma unroll
        for (int ks = 0; ks < 8; ks++) {
            int kk = ks*8 + t;
            unsigned a[4] = { qr0[kk], qr1[kk], qr0[kk+4], qr1[kk+4] };
            #pragma unroll
            for (int nt = 0; nt < 8; nt++) {
                const unsigned* kr = &Ks[(nt*8 + g)*ASTRIDE];
                unsigned bfr[2] = { kr[kk], kr[kk+4] };
                mma8(sc[nt], a, bfr);
            }
        }

        // scale + mask + online softmax (rows g and g+8; 4 lanes share a row)
        float mx0 = -1e30f, mx1 = -1e30f;
        #pragma unroll
        for (int nt = 0; nt < 8; nt++) {
            float2 mv = *(float2*)&mk[nt*8 + 2*t];
            sc[nt][0] = sc[nt][0]*0.125f + mv.x;
            sc[nt][1] = sc[nt][1]*0.125f + mv.y;
            sc[nt][2] = sc[nt][2]*0.125f + mv.x;
            sc[nt][3] = sc[nt][3]*0.125f + mv.y;
            mx0 = fmaxf(mx0, fmaxf(sc[nt][0], sc[nt][1]));
            mx1 = fmaxf(mx1, fmaxf(sc[nt][2], sc[nt][3]));
        }
        mx0 = fmaxf(mx0, __shfl_xor_sync(0xffffffffu, mx0, 1));
        mx0 = fmaxf(mx0, __shfl_xor_sync(0xffffffffu, mx0, 2));
        mx1 = fmaxf(mx1, __shfl_xor_sync(0xffffffffu, mx1, 1));
        mx1 = fmaxf(mx1, __shfl_xor_sync(0xffffffffu, mx1, 2));

        float mn0 = fmaxf(mold0, mx0), mn1 = fmaxf(mold1, mx1);
        float corr0 = __expf(mold0 - mn0), corr1 = __expf(mold1 - mn1);
        mold0 = mn0; mold1 = mn1;

        float sum0 = 0.f, sum1 = 0.f;
        #pragma unroll
        for (int nt = 0; nt < 8; nt++) {
            float p00 = __expf(sc[nt][0] - mn0), p01 = __expf(sc[nt][1] - mn0);
            float p10 = __expf(sc[nt][2] - mn1), p11 = __expf(sc[nt][3] - mn1);
            sum0 += p00 + p01; sum1 += p10 + p11;
            *(uint2*)&pr0[nt*8 + 2*t] = make_uint2(tf32cvt(p00), tf32cvt(p01));
            *(uint2*)&pr1[nt*8 + 2*t] = make_uint2(tf32cvt(p10), tf32cvt(p11));
        }
        sum0 += __shfl_xor_sync(0xffffffffu, sum0, 1);
        sum0 += __shfl_xor_sync(0xffffffffu, sum0, 2);
        sum1 += __shfl_xor_sync(0xffffffffu, sum1, 1);
        sum1 += __shfl_xor_sync(0xffffffffu, sum1, 2);
        l0 = l0*corr0 + sum0;
        l1 = l1*corr1 + sum1;
        #pragma unroll
        for (int nt = 0; nt < 8; nt++) {
            o[nt][0] *= corr0; o[nt][1] *= corr0;
            o[nt][2] *= corr1; o[nt][3] *= corr1;
        }
        __syncwarp();   // Ps is warp-private (same 16 rows); order STS->LDS

        // O += P(16x64) V(64x64):  A from Ps, B from Vt
        #pragma unroll
        for (int ks = 0; ks < 8; ks++) {
            int kk = ks*8 + t;
            unsigned a[4] = { pr0[kk], pr1[kk], pr0[kk+4], pr1[kk+4] };
            #pragma unroll
            for (int nt = 0; nt < 8; nt++) {
                const unsigned* vr = &Vt[(nt*8 + g)*ASTRIDE];
                unsigned bfr[2] = { vr[kk], vr[kk+4] };
                mma8(o[nt], a, bfr);
            }
        }
        __syncthreads();   // before next tile overwrites Ks/Vt/mk
    }

    // epilogue: normalize, write merged-head layout (b,l,d)
    float inv0 = 1.0f / l0, inv1 = 1.0f / l1;
    int row0 = q0 + w*16 + g;
    float* dst0 = g_AO + ((size_t)b*LL + row0)*DD + h*HDIM;
    float* dst1 = dst0 + (size_t)8*DD;
    #pragma unroll
    for (int nt = 0; nt < 8; nt++) {
        *(float2*)&dst0[nt*8 + 2*t] = make_float2(o[nt][0]*inv0, o[nt][1]*inv0);
        *(float2*)&dst1[nt*8 + 2*t] = make_float2(o[nt][2]*inv1, o[nt][3]*inv1);
    }
}

// =================== output projection (tf32 mma) + bias + residual ===================
__global__ __launch_bounds__(256) void outproj_mma_kernel(
    const float* __restrict__ qin, const float* __restrict__ W,
    const float* __restrict__ bias)
{
    __shared__ unsigned As[128][36];
    __shared__ unsigned Bs[64][36];

    int tid = threadIdx.x, w = tid >> 5, lane = tid & 31;
    int g = lane >> 2, t = lane & 3;
    int wm = w & 3, wn = w >> 2;
    int m0 = blockIdx.x * 128, n0 = blockIdx.y * 64;

    int lr  = tid >> 3;
    int lc4 = (tid & 7) * 4;
    const float* Ap = g_AO + (size_t)(m0 + lr) * DD + lc4;
    const float* Bp = W    + (size_t)(n0 + lr) * DD + lc4;

    float c[2][4][4] = {};

    for (int k0 = 0; k0 < DD; k0 += 32) {
        #pragma unroll
        for (int i = 0; i < 4; i++) {
            float4 v = *(const float4*)(Ap + (size_t)i*32*DD + k0);
            *(uint4*)&As[lr + i*32][lc4] = tf32cvt4(v);
        }
        #pragma unroll
        for (int i = 0; i < 2; i++) {
            float4 v = *(const float4*)(Bp + (size_t)i*32*DD + k0);
            *(uint4*)&Bs[lr + i*32][lc4] = tf32cvt4(v);
        }
        __syncthreads();
        #pragma unroll
        for (int ks = 0; ks < 4; ks++) {
            int kk = ks*8 + t;
            unsigned a[2][4], b[4][2];
            #pragma unroll
            for (int mt = 0; mt < 2; mt++) {
                int r = wm*32 + mt*16 + g;
                a[mt][0] = As[r  ][kk];
                a[mt][1] = As[r+8][kk];
                a[mt][2] = As[r  ][kk+4];
                a[mt][3] = As[r+8][kk+4];
            }
            #pragma unroll
            for (int nt = 0; nt < 4; nt++) {
                int r = wn*32 + nt*8 + g;
                b[nt][0] = Bs[r][kk];
                b[nt][1] = Bs[r][kk+4];
            }
            #pragma unroll
            for (int mt = 0; mt < 2; mt++)
                #pragma unroll
                for (int nt = 0; nt < 4; nt++)
                    mma8(c[mt][nt], a[mt], b[nt]);
        }
        __syncthreads();
    }

    #pragma unroll
    for (int mt = 0; mt < 2; mt++) {
        #pragma unroll
        for (int nt = 0; nt < 4; nt++) {
            int m = m0 + wm*32 + mt*16 + g;
            int n = n0 + wn*32 + nt*8 + 2*t;
            float2 bi = *(const float2*)&bias[n];
            {
                float2 rs = *(const float2*)&qin[(size_t)m*DD + n];
                *(float2*)&g_X[(size_t)m*DD + n] =
                    make_float2(c[mt][nt][0] + bi.x + rs.x, c[mt][nt][1] + bi.y + rs.y);
            }
            {
                int m2 = m + 8;
                float2 rs = *(const float2*)&qin[(size_t)m2*DD + n];
                *(float2*)&g_X[(size_t)m2*DD + n] =
                    make_float2(c[mt][nt][2] + bi.x + rs.x, c[mt][nt][3] + bi.y + rs.y);
            }
        }
    }
}

// =================== LayerNorm ===================
__global__ __launch_bounds__(256) void ln_kernel(
    const float* __restrict__ gamma, const float* __restrict__ beta,
    float* __restrict__ out)
{
    __shared__ float sh[18];
    int row = blockIdx.x, tid = threadIdx.x;
    const float* x = g_X + (size_t)row * DD;
    float v0 = x[tid], v1 = x[tid+256], v2 = x[tid+512];
    float s  = v0 + v1 + v2;
    float sq = v0*v0 + v1*v1 + v2*v2;
    #pragma unroll
    for (int off = 16; off > 0; off >>= 1) {
        s  += __shfl_xor_sync(0xffffffffu, s,  off);
        sq += __shfl_xor_sync(0xffffffffu, sq, off);
    }
    int wid = tid >> 5;
    if ((tid & 31) == 0) { sh[wid] = s; sh[wid + 8] = sq; }
    __syncthreads();
    if (tid == 0) {
        float S = 0.f, Q2 = 0.f;
        #pragma unroll
        for (int i = 0; i < 8; i++) { S += sh[i]; Q2 += sh[i+8]; }
        float mu  = S  * (1.0f / 768.0f);
        float var = Q2 * (1.0f / 768.0f) - mu * mu;
        sh[16] = mu;
        sh[17] = rsqrtf(var + 1e-5f);
    }
    __syncthreads();
    float mu = sh[16], rstd = sh[17];
    float* o = out + (size_t)row * DD;
    o[tid]     = (v0 - mu) * rstd * gamma[tid]     + beta[tid];
    o[tid+256] = (v1 - mu) * rstd * gamma[tid+256] + beta[tid+256];
    o[tid+512] = (v2 - mu) * rstd * gamma[tid+512] + beta[tid+512];
}

// =================== launch ===================
extern "C" void kernel_launch(void* const* d_in, const int* in_sizes, int n_in,
                              void* d_out, int out_size)
{
    const float* q     = (const float*)d_in[0];
    const float* k     = (const float*)d_in[1];
    const float* v     = (const float*)d_in[2];
    const int*   mask  = (const int*)  d_in[3];
    const float* Wq    = (const float*)d_in[4];
    const float* Wk    = (const float*)d_in[5];
    const float* Wv    = (const float*)d_in[6];
    const float* W     = (const float*)d_in[7];
    const float* bias  = (const float*)d_in[8];
    const float* gamma = (const float*)d_in[9];
    const float* beta  = (const float*)d_in[10];
    float* out = (float*)d_out;

    cudaFuncSetAttribute(attn_mma_kernel, cudaFuncAttributeMaxDynamicSharedMemorySize, ATTN_SMEM);

    qkv_mma_kernel    <<<dim3(MTOT/128, DD/64, 3), 256>>>(q, k, v, Wq, Wk, Wv);
    attn_mma_kernel   <<<dim3(LL/64, BB*HH), 128, ATTN_SMEM>>>(mask);
    outproj_mma_kernel<<<dim3(MTOT/128, DD/64), 256>>>(q, W, bias);
    ln_kernel         <<<MTOT, 256>>>(gamma, beta, out);
}